// round 1
// baseline (speedup 1.0000x reference)
#include <cuda_runtime.h>
#include <math.h>

#define B_SZ 4096
#define T_SZ 2048
#define SEG  64            // trajectory steps handled per lane (32 lanes * 64 = 2048)
#define WARPS_PER_BLOCK 8
#define DT 0.01f

// Per-batch partial sums (scratch: __device__ globals, no allocation)
__device__ float g_pq[B_SZ];
__device__ float g_pp[B_SZ];

struct M2d { double a, b, c, d; };   // [[a,b],[c,d]]

__device__ __forceinline__ M2d m2mul(const M2d& X, const M2d& Y) {
    M2d r;
    r.a = X.a * Y.a + X.b * Y.c;
    r.b = X.a * Y.b + X.b * Y.d;
    r.c = X.c * Y.a + X.d * Y.c;
    r.d = X.c * Y.b + X.d * Y.d;
    return r;
}

__global__ void __launch_bounds__(WARPS_PER_BLOCK * 32)
rollout_kernel(const float2* __restrict__ x, const float* __restrict__ y_pred)
{
    const int warp = blockIdx.x * WARPS_PER_BLOCK + (threadIdx.x >> 5);
    const int lane = threadIdx.x & 31;
    if (warp >= B_SZ) return;
    const int bidx = warp;

    // Per-batch parameters (broadcast loads)
    const float y0 = __ldg(&y_pred[bidx * 3 + 0]);
    const float y1 = __ldg(&y_pred[bidx * 3 + 1]);
    const float y2 = __ldg(&y_pred[bidx * 3 + 2]);
    const float m   = y0 + 0.1f;
    const float dtm = DT / m;      // DT/m
    const float dtk = DT * y1;     // DT*k
    const float dtl = DT * y2;     // DT*lambda

    // Exact fp32 step map (as a linear operator), lifted to double:
    // q' = q + dtm*pi ;  pi' = -dtk*q + (1 - dtl - dtk*dtm)*pi
    M2d A;
    A.a = 1.0;            A.b = (double)dtm;
    A.c = -(double)dtk;   A.d = 1.0 - (double)dtl - (double)dtk * (double)dtm;

    // cur = A^SEG  (SEG = 64 = 2^6)
    M2d cur = A;
    #pragma unroll
    for (int i = 0; i < 6; ++i) cur = m2mul(cur, cur);

    // P = (A^64)^lane via binary exponentiation (lane < 32, 5 bits)
    M2d P; P.a = 1.0; P.b = 0.0; P.c = 0.0; P.d = 1.0;
    unsigned e = (unsigned)lane;
    #pragma unroll
    for (int i = 0; i < 5; ++i) {
        if (e & 1u) P = m2mul(P, cur);
        e >>= 1;
        if (i < 4) cur = m2mul(cur, cur);
    }

    const float2* xb = x + (size_t)bidx * T_SZ;
    const float2 s0 = __ldg(&xb[0]);

    // Seed state for this lane: A^(64*lane) @ s0  (double, then down to fp32)
    float q  = (float)(P.a * (double)s0.x + P.b * (double)s0.y);
    float pi = (float)(P.c * (double)s0.x + P.d * (double)s0.y);

    const int t0 = lane * SEG;
    float w = (float)(T_SZ - t0);          // w[t] = 2048 - t
    float accq = 0.0f, accp = 0.0f;

    const float2* xt = xb + t0;
    #pragma unroll 8
    for (int s = 0; s < SEG; ++s) {
        const float2 xv = __ldg(&xt[s]);
        const float dq = q  - xv.x;
        const float dp = pi - xv.y;
        accq = fmaf(w * dq, dq, accq);
        accp = fmaf(w * dp, dp, accp);
        w -= 1.0f;
        // advance state (mirrors reference rounding closely)
        q  = fmaf(dtm, pi, q);                       // q_new = q + (DT/m)*pi
        pi = fmaf(-dtk, q, fmaf(-dtl, pi, pi));      // pi - dt*lam*pi - dt*k*q_new
    }

    // warp reduction
    #pragma unroll
    for (int off = 16; off; off >>= 1) {
        accq += __shfl_down_sync(0xffffffffu, accq, off);
        accp += __shfl_down_sync(0xffffffffu, accp, off);
    }
    if (lane == 0) { g_pq[bidx] = accq; g_pp[bidx] = accp; }
}

__global__ void __launch_bounds__(256)
finalize_kernel(const float* __restrict__ y_pred, float* __restrict__ out)
{
    __shared__ double sq[256], sp[256], sn[256];
    const int t = threadIdx.x;
    double aq = 0.0, ap = 0.0, an = 0.0;
    for (int i = t; i < B_SZ; i += 256) {
        aq += (double)g_pq[i];
        ap += (double)g_pp[i];
    }
    for (int i = t; i < B_SZ * 3; i += 256) {
        const float y = y_pred[i];
        if (y < 0.0f) an += exp(-10.0 * (double)y);
    }
    sq[t] = aq; sp[t] = ap; sn[t] = an;
    __syncthreads();
    #pragma unroll
    for (int off = 128; off; off >>= 1) {
        if (t < off) { sq[t] += sq[t + off]; sp[t] += sp[t + off]; sn[t] += sn[t + off]; }
        __syncthreads();
    }
    if (t == 0) {
        double rq = sqrt(sq[0] / (double)B_SZ);
        double rp = sqrt(sp[0] / (double)B_SZ);
        rq = fmin(rq, 1.0e15);
        rp = fmin(rp, 1.0e15);
        double pen = sn[0] / (double)(B_SZ * 3);
        pen = fmin(fmax(pen, 0.0), 1000.0);
        out[0] = (float)(0.5 * (rq + rp) + pen);
    }
}

extern "C" void kernel_launch(void* const* d_in, const int* in_sizes, int n_in,
                              void* d_out, int out_size)
{
    // Inputs: x [4096,2048,2] fp32, y_pred [4096,3] fp32 (robust to ordering)
    int xi = 0, yi = 1;
    if (n_in >= 2 && in_sizes[0] == B_SZ * 3) { xi = 1; yi = 0; }
    const float2* x      = (const float2*)d_in[xi];
    const float*  y_pred = (const float*)d_in[yi];
    float* out = (float*)d_out;

    rollout_kernel<<<B_SZ / WARPS_PER_BLOCK, WARPS_PER_BLOCK * 32>>>(x, y_pred);
    finalize_kernel<<<1, 256>>>(y_pred, out);
}

// round 2
// speedup vs baseline: 1.3819x; 1.3819x over previous
#include <cuda_runtime.h>
#include <math.h>

#define B_SZ 4096
#define T_SZ 2048
#define SEG  64            // trajectory steps per lane (32 lanes * 64 = 2048)
#define WARPS_PER_BLOCK 8
#define NBLOCKS (B_SZ / WARPS_PER_BLOCK)   // 512
#define DT 0.01f

// Per-block partials: (sum_wq2, sum_wp2, penalty_sum, unused)
__device__ float4 g_blk[NBLOCKS];

struct M2f { float a, b, c, d; };   // [[a,b],[c,d]]

__device__ __forceinline__ M2f m2mul(const M2f& X, const M2f& Y) {
    M2f r;
    r.a = fmaf(X.a, Y.a, X.b * Y.c);
    r.b = fmaf(X.a, Y.b, X.b * Y.d);
    r.c = fmaf(X.c, Y.a, X.d * Y.c);
    r.d = fmaf(X.c, Y.b, X.d * Y.d);
    return r;
}

__global__ void __launch_bounds__(WARPS_PER_BLOCK * 32)
rollout_kernel(const float2* __restrict__ x, const float* __restrict__ y_pred)
{
    __shared__ float s_q[WARPS_PER_BLOCK], s_p[WARPS_PER_BLOCK], s_n[WARPS_PER_BLOCK];

    const int wid  = threadIdx.x >> 5;
    const int lane = threadIdx.x & 31;
    const int bidx = blockIdx.x * WARPS_PER_BLOCK + wid;   // batch index

    // Per-batch parameters (broadcast loads)
    const float y0 = __ldg(&y_pred[bidx * 3 + 0]);
    const float y1 = __ldg(&y_pred[bidx * 3 + 1]);
    const float y2 = __ldg(&y_pred[bidx * 3 + 2]);
    const float m   = y0 + 0.1f;
    const float dtm = DT / m;      // DT/m
    const float dtk = DT * y1;     // DT*k
    const float dtl = DT * y2;     // DT*lambda

    // Exact fp32 step map as a linear operator:
    // q' = q + dtm*pi ;  pi' = -dtk*q' + (1 - dtl)*pi  ==>
    // [[1, dtm], [-dtk, 1 - dtl - dtk*dtm]]
    M2f A;
    A.a = 1.0f;    A.b = dtm;
    A.c = -dtk;    A.d = 1.0f - dtl - dtk * dtm;

    // cur = A^64
    M2f cur = A;
    #pragma unroll
    for (int i = 0; i < 6; ++i) cur = m2mul(cur, cur);

    // P = (A^64)^lane, binary exponentiation over 5 bits
    M2f P; P.a = 1.0f; P.b = 0.0f; P.c = 0.0f; P.d = 1.0f;
    unsigned e = (unsigned)lane;
    #pragma unroll
    for (int i = 0; i < 5; ++i) {
        if (e & 1u) P = m2mul(P, cur);
        e >>= 1;
        if (i < 4) cur = m2mul(cur, cur);
    }

    const float2* xb = x + (size_t)bidx * T_SZ;
    const float2 s0 = __ldg(&xb[0]);

    // Seed this lane's state: A^(64*lane) @ s0
    float q  = fmaf(P.a, s0.x, P.b * s0.y);
    float pi = fmaf(P.c, s0.x, P.d * s0.y);

    const int t0 = lane * SEG;
    float w = (float)(T_SZ - t0);          // w[t] = 2048 - t
    float accq = 0.0f, accp = 0.0f;

    const float2* xt = xb + t0;
    #pragma unroll 8
    for (int s = 0; s < SEG; ++s) {
        const float2 xv = __ldg(&xt[s]);
        const float dq = q  - xv.x;
        const float dp = pi - xv.y;
        accq = fmaf(w * dq, dq, accq);
        accp = fmaf(w * dp, dp, accp);
        w -= 1.0f;
        q  = fmaf(dtm, pi, q);                       // q_new = q + (DT/m)*pi
        pi = fmaf(-dtk, q, fmaf(-dtl, pi, pi));      // pi_new
    }

    // warp reduction
    #pragma unroll
    for (int off = 16; off; off >>= 1) {
        accq += __shfl_down_sync(0xffffffffu, accq, off);
        accp += __shfl_down_sync(0xffffffffu, accp, off);
    }

    if (lane == 0) {
        // penalty contribution for this batch's 3 params
        float pen = 0.0f;
        if (y0 < 0.0f) pen += expf(-10.0f * y0);
        if (y1 < 0.0f) pen += expf(-10.0f * y1);
        if (y2 < 0.0f) pen += expf(-10.0f * y2);
        s_q[wid] = accq; s_p[wid] = accp; s_n[wid] = pen;
    }
    __syncthreads();

    // fixed-order block reduction (deterministic)
    if (threadIdx.x == 0) {
        float bq = 0.0f, bp = 0.0f, bn = 0.0f;
        #pragma unroll
        for (int i = 0; i < WARPS_PER_BLOCK; ++i) { bq += s_q[i]; bp += s_p[i]; bn += s_n[i]; }
        g_blk[blockIdx.x] = make_float4(bq, bp, bn, 0.0f);
    }
}

__global__ void __launch_bounds__(NBLOCKS)
finalize_kernel(float* __restrict__ out)
{
    __shared__ double sq[NBLOCKS], sp[NBLOCKS], sn[NBLOCKS];
    const int t = threadIdx.x;
    const float4 v = g_blk[t];
    sq[t] = (double)v.x; sp[t] = (double)v.y; sn[t] = (double)v.z;
    __syncthreads();
    #pragma unroll
    for (int off = NBLOCKS / 2; off; off >>= 1) {
        if (t < off) { sq[t] += sq[t + off]; sp[t] += sp[t + off]; sn[t] += sn[t + off]; }
        __syncthreads();
    }
    if (t == 0) {
        double rq = sqrt(sq[0] / (double)B_SZ);
        double rp = sqrt(sp[0] / (double)B_SZ);
        rq = fmin(rq, 1.0e15);
        rp = fmin(rp, 1.0e15);
        double pen = sn[0] / (double)(B_SZ * 3);
        pen = fmin(fmax(pen, 0.0), 1000.0);
        out[0] = (float)(0.5 * (rq + rp) + pen);
    }
}

extern "C" void kernel_launch(void* const* d_in, const int* in_sizes, int n_in,
                              void* d_out, int out_size)
{
    // Inputs: x [4096,2048,2] fp32, y_pred [4096,3] fp32 (robust to ordering)
    int xi = 0, yi = 1;
    if (n_in >= 2 && in_sizes[0] == B_SZ * 3) { xi = 1; yi = 0; }
    const float2* x      = (const float2*)d_in[xi];
    const float*  y_pred = (const float*)d_in[yi];
    float* out = (float*)d_out;

    rollout_kernel<<<NBLOCKS, WARPS_PER_BLOCK * 32>>>(x, y_pred);
    finalize_kernel<<<1, NBLOCKS>>>(out);
}

// round 3
// speedup vs baseline: 3.9659x; 2.8699x over previous
#include <cuda_runtime.h>
#include <math.h>

#define B_SZ 4096
#define T_SZ 2048
#define WARPS_PER_BLOCK 8
#define NBLOCKS (B_SZ / WARPS_PER_BLOCK)   // 512
#define NWIN 32                             // 32 windows of 64 timesteps
#define DT 0.01f

// Per-block partials: (sum_wq2, sum_wp2, penalty_sum, unused)
__device__ float4 g_blk[NBLOCKS];
__device__ unsigned g_cnt = 0;

struct M2f { float a, b, c, d; };   // [[a,b],[c,d]]

__device__ __forceinline__ M2f m2mul(const M2f& X, const M2f& Y) {
    M2f r;
    r.a = fmaf(X.a, Y.a, X.b * Y.c);
    r.b = fmaf(X.a, Y.b, X.b * Y.d);
    r.c = fmaf(X.c, Y.a, X.d * Y.c);
    r.d = fmaf(X.c, Y.b, X.d * Y.d);
    return r;
}

__global__ void __launch_bounds__(WARPS_PER_BLOCK * 32)
rollout_kernel(const float4* __restrict__ x4, const float* __restrict__ y_pred,
               float* __restrict__ out)
{
    __shared__ float s_q[WARPS_PER_BLOCK], s_p[WARPS_PER_BLOCK], s_n[WARPS_PER_BLOCK];
    __shared__ double fsq[256], fsp[256], fsn[256];
    __shared__ bool isLast;

    const int wid  = threadIdx.x >> 5;
    const int lane = threadIdx.x & 31;
    const int bidx = blockIdx.x * WARPS_PER_BLOCK + wid;   // batch index

    // Per-batch parameters (broadcast loads)
    const float y0 = __ldg(&y_pred[bidx * 3 + 0]);
    const float y1 = __ldg(&y_pred[bidx * 3 + 1]);
    const float y2 = __ldg(&y_pred[bidx * 3 + 2]);
    const float m   = y0 + 0.1f;
    const float dtm = DT / m;
    const float dtk = DT * y1;
    const float dtl = DT * y2;

    // One fp32 step as a linear operator:
    // q' = q + dtm*pi ; pi' = -dtk*q' + (1-dtl)*pi
    M2f A;
    A.a = 1.0f;   A.b = dtm;
    A.c = -dtk;   A.d = 1.0f - dtl - dtk * dtm;

    // P = (A^2)^lane, and M64 = A^64 falls out of the same squaring chain.
    M2f cur = m2mul(A, A);                        // A^2
    M2f P; P.a = 1.0f; P.b = 0.0f; P.c = 0.0f; P.d = 1.0f;
    unsigned e = (unsigned)lane;
    #pragma unroll
    for (int i = 0; i < 5; ++i) {
        if (e & 1u) P = m2mul(P, cur);
        e >>= 1;
        cur = m2mul(cur, cur);                    // ends at A^64
    }
    const M2f M64 = cur;

    const float4* xr = x4 + (size_t)bidx * (T_SZ / 2);
    const float4 x0 = __ldg(&xr[0]);              // (q0, pi0, q1-true, pi1-true)

    // Seed this lane's state at t = 2*lane
    float q  = fmaf(P.a, x0.x, P.b * x0.y);
    float pi = fmaf(P.c, x0.x, P.d * x0.y);

    float w0 = (float)(T_SZ - 2 * lane);          // weight at t = 2*lane
    float accq = 0.0f, accp = 0.0f;

    #pragma unroll 4
    for (int w = 0; w < NWIN; ++w) {
        // lane j covers timesteps t = 64w + 2j and t+1  -> coalesced 512B/warp
        const float4 xv = __ldg(&xr[w * 32 + lane]);

        const float dq0 = q  - xv.x;
        const float dp0 = pi - xv.y;
        accq = fmaf(w0 * dq0, dq0, accq);
        accp = fmaf(w0 * dp0, dp0, accp);

        // one exact fp32 step for t+1 (doesn't clobber window state)
        const float q1  = fmaf(dtm, pi, q);
        const float pi1 = fmaf(-dtk, q1, fmaf(-dtl, pi, pi));
        const float dq1 = q1  - xv.z;
        const float dp1 = pi1 - xv.w;
        const float w1 = w0 - 1.0f;
        accq = fmaf(w1 * dq1, dq1, accq);
        accp = fmaf(w1 * dp1, dp1, accp);

        // advance window state by A^64
        const float qn  = fmaf(M64.a, q, M64.b * pi);
        const float pin = fmaf(M64.c, q, M64.d * pi);
        q = qn; pi = pin;
        w0 -= 64.0f;
    }

    // warp reduction
    #pragma unroll
    for (int off = 16; off; off >>= 1) {
        accq += __shfl_down_sync(0xffffffffu, accq, off);
        accp += __shfl_down_sync(0xffffffffu, accp, off);
    }

    if (lane == 0) {
        float pen = 0.0f;
        if (y0 < 0.0f) pen += expf(-10.0f * y0);
        if (y1 < 0.0f) pen += expf(-10.0f * y1);
        if (y2 < 0.0f) pen += expf(-10.0f * y2);
        s_q[wid] = accq; s_p[wid] = accp; s_n[wid] = pen;
    }
    __syncthreads();

    if (threadIdx.x == 0) {
        float bq = 0.0f, bp = 0.0f, bn = 0.0f;
        #pragma unroll
        for (int i = 0; i < WARPS_PER_BLOCK; ++i) { bq += s_q[i]; bp += s_p[i]; bn += s_n[i]; }
        g_blk[blockIdx.x] = make_float4(bq, bp, bn, 0.0f);
        __threadfence();
        unsigned c = atomicAdd(&g_cnt, 1u);
        isLast = (c == NBLOCKS - 1);
    }
    __syncthreads();

    // Last block: deterministic fixed-order final reduction
    if (isLast) {
        const int t = threadIdx.x;
        const float4 v1 = __ldcg(&g_blk[t]);
        const float4 v2 = __ldcg(&g_blk[t + 256]);
        fsq[t] = (double)v1.x + (double)v2.x;
        fsp[t] = (double)v1.y + (double)v2.y;
        fsn[t] = (double)v1.z + (double)v2.z;
        __syncthreads();
        #pragma unroll
        for (int off = 128; off; off >>= 1) {
            if (t < off) { fsq[t] += fsq[t + off]; fsp[t] += fsp[t + off]; fsn[t] += fsn[t + off]; }
            __syncthreads();
        }
        if (t == 0) {
            double rq = sqrt(fsq[0] / (double)B_SZ);
            double rp = sqrt(fsp[0] / (double)B_SZ);
            rq = fmin(rq, 1.0e15);
            rp = fmin(rp, 1.0e15);
            double pen = fsn[0] / (double)(B_SZ * 3);
            pen = fmin(fmax(pen, 0.0), 1000.0);
            out[0] = (float)(0.5 * (rq + rp) + pen);
            g_cnt = 0;                 // reset for next graph replay
        }
    }
}

extern "C" void kernel_launch(void* const* d_in, const int* in_sizes, int n_in,
                              void* d_out, int out_size)
{
    int xi = 0, yi = 1;
    if (n_in >= 2 && in_sizes[0] == B_SZ * 3) { xi = 1; yi = 0; }
    const float4* x4     = (const float4*)d_in[xi];
    const float*  y_pred = (const float*)d_in[yi];
    float* out = (float*)d_out;

    rollout_kernel<<<NBLOCKS, WARPS_PER_BLOCK * 32>>>(x4, y_pred, out);
}